// round 13
// baseline (speedup 1.0000x reference)
#include <cuda_runtime.h>
#include <math.h>

namespace {
constexpr int Bn = 4, Cn = 192, Tn = 2048, Hn = 2, Kd = 96;
constexpr int TQ = 64;
constexpr int BAND = 256;
constexpr int WIN = 4;
constexpr int SPAN = TQ + 2 * BAND;   // 576
constexpr int NCH = SPAN / 64;        // 9
constexpr int KVS  = 100;             // mult of 4 (cp.async 16B rows), even (LDS.64)
constexpr int PSTR = 80;
constexpr int PASTR = 196;            // proj A stride: mult 4 -> LDS.128 rows
constexpr int PWSTR = 194;            // proj W stride: ==2 mod 32 -> conflict-free LDS.64
constexpr int ATTN_SMEM_FLOATS = 3 * TQ * KVS   // qs, Ks, Vs
                               + TQ * PSTR      // P
                               + TQ * 12        // rq
                               + TQ * 12        // pTap
                               + TQ             // lr
                               + 260            // prox
                               + 128;           // mrow u64[64]
constexpr int PROJ_SMEM_BYTES = 64 * (PASTR + PWSTR) * 4;   // 99.8KB -> 2 CTAs/SM
constexpr int OASTR = 196;
constexpr int OWSTR = 194;
constexpr int OUT_SMEM_BYTES = 64 * (OASTR + OWSTR) * 4;
}

__device__ __align__(16) float g_q[Bn * Tn * Cn];
__device__ __align__(16) float g_k[Bn * Tn * Cn];
__device__ __align__(16) float g_v[Bn * Tn * Cn];
__device__ __align__(16) float g_att[Bn * Tn * Cn];

typedef unsigned long long u64t;

__device__ __forceinline__ u64t fma2(u64t a, u64t b, u64t c) {
    u64t d;
    asm("fma.rn.f32x2 %0, %1, %2, %3;" : "=l"(d) : "l"(a), "l"(b), "l"(c));
    return d;
}
__device__ __forceinline__ float lohi_sum(u64t v) {
    float2 f = *reinterpret_cast<float2*>(&v);
    return f.x + f.y;
}
__device__ __forceinline__ float2 unpk(u64t v) { return *reinterpret_cast<float2*>(&v); }
__device__ __forceinline__ u64t lds2(const float* p) {
    return *reinterpret_cast<const u64t*>(p);
}
__device__ __forceinline__ u64t dup2(float p) {
    u64t r;
    asm("mov.b64 %0, {%1, %1};" : "=l"(r) : "f"(p));
    return r;
}
__device__ __forceinline__ void cpa16(float* s, const float* g) {
    asm volatile("cp.async.cg.shared.global [%0], [%1], 16;"
                 :: "r"((unsigned)__cvta_generic_to_shared(s)), "l"(g));
}
__device__ __forceinline__ void cpa_commit() { asm volatile("cp.async.commit_group;"); }
__device__ __forceinline__ void cpa_wait0()  { asm volatile("cp.async.wait_group 0;"); }

// ---------------------------------------------------------------------------
// Q/K/V projections: 64x64 tile, 4x4 microtile, 4-wide kk loop, 2 CTAs/SM.
// A staged [t][196] (LDS.128 broadcast side), W staged [d][194] (conflict-free
// LDS.64 side). Fill mappings chosen so all 32 store banks are distinct.
// grid (32, 3, 12), block (16,16)
// ---------------------------------------------------------------------------
__global__ void __launch_bounds__(256, 2)
proj_kernel(const float* __restrict__ xin, const float* __restrict__ cin,
            const float* __restrict__ Wq, const float* __restrict__ bq,
            const float* __restrict__ Wk, const float* __restrict__ bk,
            const float* __restrict__ Wv, const float* __restrict__ bv) {
    extern __shared__ float smp[];
    float* a_s = smp;               // [64 t][196 kk]
    float* w_s = smp + 64 * PASTR;  // [64 d][194 kk]
    const int which = blockIdx.z % 3;
    const int b = blockIdx.z / 3;
    const float* in   = (which == 0) ? xin : cin;
    const float* W    = (which == 0) ? Wq : (which == 1) ? Wk : Wv;
    const float* bias = (which == 0) ? bq : (which == 1) ? bk : bv;
    float* out        = (which == 0) ? g_q : (which == 1) ? g_k : g_v;
    const int t0 = blockIdx.x * 64, d0 = blockIdx.y * 64;
    const int tx = threadIdx.x, ty = threadIdx.y, tid = ty * 16 + tx;
    const int lane = tid & 31, wrp = tid >> 5;
    const float* inb = in + b * Cn * Tn;

    // ---- A fill: mapping (l2 = lane&1, kl = lane>>1) ----
    // kk = kl + 16*((wrp&1) + 2*r), t4 = 4*l2 + 8*(wrp>>1) + 32*ph
    // store bank = (16*l2 + kl + const) mod 32 -> all 32 distinct.
    {
        const int l2 = lane & 1, kl = lane >> 1;
        const int tbase = 4 * l2 + 8 * (wrp >> 1);
        const int kbase = kl + 16 * (wrp & 1);
        float4 va[12];
#pragma unroll
        for (int r = 0; r < 6; r++)
#pragma unroll
            for (int ph = 0; ph < 2; ph++) {
                int kk = kbase + 32 * r;
                int t4 = tbase + 32 * ph;
                va[r * 2 + ph] = *reinterpret_cast<const float4*>(inb + kk * Tn + t0 + t4);
            }
#pragma unroll
        for (int r = 0; r < 6; r++)
#pragma unroll
            for (int ph = 0; ph < 2; ph++) {
                int kk = kbase + 32 * r;
                int t4 = tbase + 32 * ph;
                float4 v = va[r * 2 + ph];
                a_s[(t4 + 0) * PASTR + kk] = v.x;
                a_s[(t4 + 1) * PASTR + kk] = v.y;
                a_s[(t4 + 2) * PASTR + kk] = v.z;
                a_s[(t4 + 3) * PASTR + kk] = v.w;
            }
    }
    // ---- W fill: (la = lane&3, kl = lane>>2), stride 194 ----
    // store bank = (8*la + kl + const) mod 32 -> all 32 distinct.
    {
        const int la = lane & 3, kl = lane >> 2;
        float4 vw[12];
#pragma unroll
        for (int r = 0; r < 3; r++)
#pragma unroll
            for (int ph = 0; ph < 4; ph++) {
                int kk = kl + 8 * wrp + 64 * r;
                int d4 = 4 * la + 16 * ph;
                vw[r * 4 + ph] = *reinterpret_cast<const float4*>(W + kk * Cn + d0 + d4);
            }
#pragma unroll
        for (int r = 0; r < 3; r++)
#pragma unroll
            for (int ph = 0; ph < 4; ph++) {
                int kk = kl + 8 * wrp + 64 * r;
                int d4 = 4 * la + 16 * ph;
                float4 v = vw[r * 4 + ph];
                w_s[(d4 + 0) * PWSTR + kk] = v.x;
                w_s[(d4 + 1) * PWSTR + kk] = v.y;
                w_s[(d4 + 2) * PWSTR + kk] = v.z;
                w_s[(d4 + 3) * PWSTR + kk] = v.w;
            }
    }
    __syncthreads();

    u64t acc2[4][4] = {};
#pragma unroll 4
    for (int kk = 0; kk < Cn; kk += 4) {
        float4 a4[4];
        u64t w2[4][2];
#pragma unroll
        for (int i = 0; i < 4; i++)
            a4[i] = *reinterpret_cast<const float4*>(&a_s[(ty + 16 * i) * PASTR + kk]);
#pragma unroll
        for (int j = 0; j < 4; j++) {
            w2[j][0] = lds2(&w_s[(tx + 16 * j) * PWSTR + kk]);
            w2[j][1] = lds2(&w_s[(tx + 16 * j) * PWSTR + kk + 2]);
        }
#pragma unroll
        for (int i = 0; i < 4; i++) {
            const u64t* aa = reinterpret_cast<const u64t*>(&a4[i]);
#pragma unroll
            for (int j = 0; j < 4; j++) {
                acc2[i][j] = fma2(aa[0], w2[j][0], acc2[i][j]);
                acc2[i][j] = fma2(aa[1], w2[j][1], acc2[i][j]);
            }
        }
    }
    float* ob = out + b * Tn * Cn;
#pragma unroll
    for (int i = 0; i < 4; i++) {
        int t = t0 + ty + 16 * i;
#pragma unroll
        for (int j = 0; j < 4; j++) {
            int d = d0 + tx + 16 * j;
            ob[t * Cn + d] = lohi_sum(acc2[i][j]) + bias[d];
        }
    }
}

// ---------------------------------------------------------------------------
// Single-pass banded attention (R10 version — best measured):
//  - warp-ballot mask producer per chunk (coalesced, overlaps cp.async wait)
//  - split K/V prefetch: K overlaps PV, V issued after PV
// ---------------------------------------------------------------------------
__global__ void __launch_bounds__(256, 2)
attn_kernel(const float* __restrict__ embk, const float* __restrict__ embv,
            const int* __restrict__ mask) {
    extern __shared__ float sm[];
    float* qs   = sm;                     // [64][100]
    float* Ks   = qs + TQ * KVS;          // [64][100]
    float* Vs   = Ks + TQ * KVS;          // [64][100]
    float* P    = Vs + TQ * KVS;          // [64][80]
    float* rq   = P + TQ * PSTR;          // [64][12]
    float* pTap = rq + TQ * 12;           // [64][12]
    float* lr   = pTap + TQ * 12;         // [64]
    float* prox = lr + TQ;                // [260]
    u64t*  mrow = reinterpret_cast<u64t*>(prox + 260);  // [64]

    const int tx = threadIdx.x, ty = threadIdx.y;
    const int tid = ty * 16 + tx;
    const int lane = tid & 31, wrp = tid >> 5;
    const int b = blockIdx.y / Hn, h = blockIdx.y % Hn;
    const int t0 = blockIdx.x * TQ;
    const int sbase = t0 - BAND;

    const float* Qb = g_q + (b * Tn) * Cn + h * Kd;
    const float* Kb = g_k + (b * Tn) * Cn + h * Kd;
    const float* Vb = g_v + (b * Tn) * Cn + h * Kd;
    const int* mb = mask + b * Tn * Tn;

    // issue chunk 0 K+V loads
#pragma unroll
    for (int r = 0; r < 6; r++) {
        int idx = tid + 256 * r;
        int row = idx / 24, c4 = (idx % 24) * 4;
        int s = sbase + row;
        int sc = s < 0 ? 0 : (s >= Tn ? Tn - 1 : s);
        cpa16(&Ks[row * KVS + c4], Kb + sc * Cn + c4);
        cpa16(&Vs[row * KVS + c4], Vb + sc * Cn + c4);
    }
    cpa_commit();

    for (int i = tid; i < TQ * 12; i += 256) pTap[i] = 0.f;
    for (int i = tid; i <= BAND; i += 256) prox[i] = log1pf((float)i);

    // load Q (pre-scaled)
    const float qsc = 0.10206207261596575f;
#pragma unroll
    for (int r = 0; r < 6; r++) {
        int idx = tid + 256 * r;
        int row = idx / 24, c4 = (idx % 24) * 4;
        float4 v = *reinterpret_cast<const float4*>(Qb + (t0 + row) * Cn + c4);
        float* d = qs + row * KVS + c4;
        d[0] = v.x * qsc; d[1] = v.y * qsc; d[2] = v.z * qsc; d[3] = v.w * qsc;
    }
    __syncthreads();   // qs visible for rq

    // rel-K per-query logits
    for (int idx = tid; idx < TQ * 9; idx += 256) {
        int q = idx / 9, m = idx - q * 9;
        const float* e  = embk + m * Kd;
        const float* qp = qs + q * KVS;
        float s = 0.f;
#pragma unroll 8
        for (int kk = 0; kk < Kd; kk++) s += qp[kk] * e[kk];
        rq[q * 12 + m] = s;
    }

    float o[4][6] = {};
    float lsum[4] = {};

    for (int ch = 0; ch < NCH; ch++) {
        // mask ballot (overlaps cp.async wait)
        {
            int s0 = sbase + ch * 64;
#pragma unroll
            for (int rr = 0; rr < 8; rr++) {
                int t = t0 + 8 * wrp + rr;
                int s1 = s0 + lane, s2 = s0 + lane + 32;
                int d1 = s1 - t, d2 = s2 - t;
                bool v1 = (s1 >= 0) && (s1 < Tn) && (d1 <= BAND) && (d1 >= -BAND);
                bool v2 = (s2 >= 0) && (s2 < Tn) && (d2 <= BAND) && (d2 >= -BAND);
                if (v1) v1 = (mb[t * Tn + s1] != 0);
                if (v2) v2 = (mb[t * Tn + s2] != 0);
                unsigned b1 = __ballot_sync(0xffffffffu, v1);
                unsigned b2 = __ballot_sync(0xffffffffu, v2);
                if (lane == 0) mrow[8 * wrp + rr] = ((u64t)b2 << 32) | (u64t)b1;
            }
        }
        cpa_wait0();
        __syncthreads();   // Ks/Vs(ch) + mrow visible

        // QK^T, kk paired into f32x2
        u64t acc2[4][4] = {};
#pragma unroll 4
        for (int kk = 0; kk < Kd; kk += 2) {
            u64t q2[4], k2[4];
#pragma unroll
            for (int i = 0; i < 4; i++) q2[i] = lds2(&qs[(ty + 16 * i) * KVS + kk]);
#pragma unroll
            for (int j = 0; j < 4; j++) k2[j] = lds2(&Ks[(tx + 16 * j) * KVS + kk]);
#pragma unroll
            for (int i = 0; i < 4; i++)
#pragma unroll
                for (int j = 0; j < 4; j++) acc2[i][j] = fma2(q2[i], k2[j], acc2[i][j]);
        }

        // epilogue: rel-k tap + proximal bias + mask bit + exp
#pragma unroll
        for (int i = 0; i < 4; i++) {
            int q = ty + 16 * i, t = t0 + q;
            u64t rm = mrow[q];
#pragma unroll
            for (int j = 0; j < 4; j++) {
                int sl = tx + 16 * j;
                int s = sbase + ch * 64 + sl;
                int d = s - t;
                int ad = d < 0 ? -d : d;
                float v = lohi_sum(acc2[i][j]);
                if (ad <= WIN) v += rq[q * 12 + d + WIN];
                v -= prox[ad <= BAND ? ad : BAND];
                float e = ((rm >> sl) & 1ull) ? __expf(v) : 0.f;
                P[q * PSTR + sl] = e;
                if (ad <= WIN) pTap[q * 12 + d + WIN] = e;
                lsum[i] += e;
            }
        }
        __syncthreads();   // P visible; all warps done with Ks

        // prefetch next K now -> overlaps the PV phase below
        if (ch + 1 < NCH) {
#pragma unroll
            for (int r = 0; r < 6; r++) {
                int idx = tid + 256 * r;
                int row = idx / 24, c4 = (idx % 24) * 4;
                int s = sbase + (ch + 1) * 64 + row;
                int sc = s < 0 ? 0 : (s >= Tn ? Tn - 1 : s);
                cpa16(&Ks[row * KVS + c4], Kb + sc * Cn + c4);
            }
            cpa_commit();
        }

        // O += P @ V, d-paired (row-major V)
        {
            u64t o2[4][3] = {};
#pragma unroll 2
            for (int sl = 0; sl < 64; sl++) {
                u64t pd[4], v2[3];
#pragma unroll
                for (int i = 0; i < 4; i++) pd[i] = dup2(P[(ty + 16 * i) * PSTR + sl]);
#pragma unroll
                for (int jj = 0; jj < 3; jj++) v2[jj] = lds2(&Vs[sl * KVS + 2 * tx + 32 * jj]);
#pragma unroll
                for (int i = 0; i < 4; i++)
#pragma unroll
                    for (int jj = 0; jj < 3; jj++) o2[i][jj] = fma2(pd[i], v2[jj], o2[i][jj]);
            }
#pragma unroll
            for (int i = 0; i < 4; i++)
#pragma unroll
                for (int jj = 0; jj < 3; jj++) {
                    float2 f = unpk(o2[i][jj]);
                    o[i][2 * jj] += f.x;
                    o[i][2 * jj + 1] += f.y;
                }
        }
        __syncthreads();   // PV done with Vs/P

        // now Vs is free: issue next V
        if (ch + 1 < NCH) {
#pragma unroll
            for (int r = 0; r < 6; r++) {
                int idx = tid + 256 * r;
                int row = idx / 24, c4 = (idx % 24) * 4;
                int s = sbase + (ch + 1) * 64 + row;
                int sc = s < 0 ? 0 : (s >= Tn ? Tn - 1 : s);
                cpa16(&Vs[row * KVS + c4], Vb + sc * Cn + c4);
            }
            cpa_commit();
        }
    }

    // reduce row sums across the 16 tx lanes
#pragma unroll
    for (int i = 0; i < 4; i++) {
        float l = lsum[i];
        l += __shfl_xor_sync(0xffffffffu, l, 1);
        l += __shfl_xor_sync(0xffffffffu, l, 2);
        l += __shfl_xor_sync(0xffffffffu, l, 4);
        l += __shfl_xor_sync(0xffffffffu, l, 8);
        if (tx == 0) lr[ty + 16 * i] = l;
    }
    __syncthreads();

    // rel-V taps + normalize + store
#pragma unroll
    for (int i = 0; i < 4; i++) {
        int q = ty + 16 * i;
        float inv = 1.0f / lr[q];
#pragma unroll
        for (int m = 0; m < 9; m++) {
            float p = pTap[q * 12 + m];
#pragma unroll
            for (int jj = 0; jj < 3; jj++) {
                float2 e2 = *reinterpret_cast<const float2*>(embv + m * Kd + 2 * tx + 32 * jj);
                o[i][2 * jj]     += p * e2.x;
                o[i][2 * jj + 1] += p * e2.y;
            }
        }
        float* ob = g_att + (b * Tn + t0 + q) * Cn + h * Kd;
#pragma unroll
        for (int jj = 0; jj < 3; jj++) {
            float2 w;
            w.x = o[i][2 * jj] * inv;
            w.y = o[i][2 * jj + 1] * inv;
            *reinterpret_cast<float2*>(ob + 2 * tx + 32 * jj) = w;
        }
    }
}

// ---------------------------------------------------------------------------
// Output projection + transpose (R7 version, conflict-free strides).
// ---------------------------------------------------------------------------
__global__ void __launch_bounds__(256)
outproj_kernel(const float* __restrict__ Wo, const float* __restrict__ bo,
               float* __restrict__ out) {
    extern __shared__ float smp[];
    float* a_s = smp;                // [64 t][OASTR dd]
    float* w_s = smp + 64 * OASTR;   // [64 co][OWSTR dd]
    const int b = blockIdx.z;
    const int t0 = blockIdx.x * 64, c0 = blockIdx.y * 64;
    const int tx = threadIdx.x, ty = threadIdx.y, tid = ty * 16 + tx;
    const int lane = tid & 31, wrp = tid >> 5;
    const int la = lane & 3, kl = lane >> 2;
    const float* ab = g_att + b * Tn * Cn;

#pragma unroll
    for (int r = 0; r < 12; r++) {
        int idx = tid + 256 * r;
        int t = idx / 48, dq = (idx % 48) * 4;
        cpa16(&a_s[t * OASTR + dq], ab + (t0 + t) * Cn + dq);
    }
    cpa_commit();
    {
        float4 vw[12];
#pragma unroll
        for (int r = 0; r < 3; r++)
#pragma unroll
            for (int ph = 0; ph < 4; ph++) {
                int kk = kl + 8 * wrp + 64 * r;
                int d4 = 4 * la + 16 * ph;
                vw[r * 4 + ph] = *reinterpret_cast<const float4*>(Wo + kk * Cn + c0 + d4);
            }
#pragma unroll
        for (int r = 0; r < 3; r++)
#pragma unroll
            for (int ph = 0; ph < 4; ph++) {
                int kk = kl + 8 * wrp + 64 * r;
                int d4 = 4 * la + 16 * ph;
                float4 v = vw[r * 4 + ph];
                w_s[(d4 + 0) * OWSTR + kk] = v.x;
                w_s[(d4 + 1) * OWSTR + kk] = v.y;
                w_s[(d4 + 2) * OWSTR + kk] = v.z;
                w_s[(d4 + 3) * OWSTR + kk] = v.w;
            }
    }
    cpa_wait0();
    __syncthreads();

    u64t acc2[4][4] = {};
#pragma unroll 8
    for (int kk = 0; kk < Cn; kk += 2) {
        u64t w2[4], a2[4];
#pragma unroll
        for (int i = 0; i < 4; i++) w2[i] = lds2(&w_s[(ty + 16 * i) * OWSTR + kk]);
#pragma unroll
        for (int j = 0; j < 4; j++) a2[j] = lds2(&a_s[(tx + 16 * j) * OASTR + kk]);
#pragma unroll
        for (int i = 0; i < 4; i++)
#pragma unroll
            for (int j = 0; j < 4; j++) acc2[i][j] = fma2(w2[i], a2[j], acc2[i][j]);
    }
#pragma unroll
    for (int i = 0; i < 4; i++) {
        int co = c0 + ty + 16 * i;
        float bb = bo[co];
#pragma unroll
        for (int j = 0; j < 4; j++)
            out[(b * Cn + co) * Tn + t0 + tx + 16 * j] = lohi_sum(acc2[i][j]) + bb;
    }
}

// ---------------------------------------------------------------------------
extern "C" void kernel_launch(void* const* d_in, const int* in_sizes, int n_in,
                              void* d_out, int out_size) {
    (void)in_sizes; (void)n_in; (void)out_size;
    const float* x   = (const float*)d_in[0];
    const float* c   = (const float*)d_in[1];
    const float* Wq  = (const float*)d_in[2];
    const float* bq  = (const float*)d_in[3];
    const float* Wk  = (const float*)d_in[4];
    const float* bk  = (const float*)d_in[5];
    const float* Wv  = (const float*)d_in[6];
    const float* bv  = (const float*)d_in[7];
    const float* Wo  = (const float*)d_in[8];
    const float* bo  = (const float*)d_in[9];
    const float* ek  = (const float*)d_in[10];
    const float* ev  = (const float*)d_in[11];
    const int*   msk = (const int*)d_in[12];

    const int attn_smem = ATTN_SMEM_FLOATS * (int)sizeof(float);
    cudaFuncSetAttribute(attn_kernel, cudaFuncAttributeMaxDynamicSharedMemorySize, attn_smem);
    cudaFuncSetAttribute(proj_kernel, cudaFuncAttributeMaxDynamicSharedMemorySize, PROJ_SMEM_BYTES);
    cudaFuncSetAttribute(outproj_kernel, cudaFuncAttributeMaxDynamicSharedMemorySize, OUT_SMEM_BYTES);

    proj_kernel<<<dim3(Tn / 64, Cn / 64, Bn * 3), dim3(16, 16), PROJ_SMEM_BYTES>>>(
        x, c, Wq, bq, Wk, bk, Wv, bv);
    attn_kernel<<<dim3(Tn / TQ, Bn * Hn), dim3(16, 16), attn_smem>>>(ek, ev, msk);
    outproj_kernel<<<dim3(Tn / 64, Cn / 64, Bn), dim3(16, 16), OUT_SMEM_BYTES>>>(
        Wo, bo, (float*)d_out);
}

// round 14
// speedup vs baseline: 1.0301x; 1.0301x over previous
#include <cuda_runtime.h>
#include <math.h>

namespace {
constexpr int Bn = 4, Cn = 192, Tn = 2048, Hn = 2, Kd = 96;
constexpr int TQ = 64;
constexpr int BAND = 256;
constexpr int WIN = 4;
constexpr int SPAN = TQ + 2 * BAND;   // 576
constexpr int NCH = SPAN / 64;        // 9
constexpr int KVS  = 100;             // mult of 4 (cp.async 16B rows), even (LDS.64)
constexpr int PSTR = 80;
constexpr int ASTR = 196;             // proj A staging stride (16B rows for LDS.128)
constexpr int WSTR2 = 194;            // proj W staging stride (==2 mod 32, conflict-free)
constexpr int ATTN_SMEM_FLOATS = 3 * TQ * KVS   // qs, Ks, Vs
                               + TQ * PSTR      // P
                               + TQ * 12        // rq
                               + TQ * 12        // pTap
                               + TQ             // lr
                               + 260            // prox
                               + NCH * TQ * 2;  // mrows u64[9][64]
constexpr int GEMM_SMEM_BYTES = (128 * ASTR + 64 * WSTR2) * 4;   // 150.0KB
constexpr int OASTR = 196;
constexpr int OWSTR = 194;
constexpr int OUT_SMEM_BYTES = 64 * (OASTR + OWSTR) * 4;
}

__device__ __align__(16) float g_q[Bn * Tn * Cn];
__device__ __align__(16) float g_k[Bn * Tn * Cn];
__device__ __align__(16) float g_v[Bn * Tn * Cn];
__device__ __align__(16) float g_att[Bn * Tn * Cn];

typedef unsigned long long u64t;

__device__ __forceinline__ u64t fma2(u64t a, u64t b, u64t c) {
    u64t d;
    asm("fma.rn.f32x2 %0, %1, %2, %3;" : "=l"(d) : "l"(a), "l"(b), "l"(c));
    return d;
}
__device__ __forceinline__ float lohi_sum(u64t v) {
    float2 f = *reinterpret_cast<float2*>(&v);
    return f.x + f.y;
}
__device__ __forceinline__ float2 unpk(u64t v) { return *reinterpret_cast<float2*>(&v); }
__device__ __forceinline__ u64t lds2(const float* p) {
    return *reinterpret_cast<const u64t*>(p);
}
__device__ __forceinline__ u64t dup2(float p) {
    u64t r;
    asm("mov.b64 %0, {%1, %1};" : "=l"(r) : "f"(p));
    return r;
}
__device__ __forceinline__ void cpa16(float* s, const float* g) {
    asm volatile("cp.async.cg.shared.global [%0], [%1], 16;"
                 :: "r"((unsigned)__cvta_generic_to_shared(s)), "l"(g));
}
__device__ __forceinline__ void cpa_commit() { asm volatile("cp.async.commit_group;"); }
__device__ __forceinline__ void cpa_wait0()  { asm volatile("cp.async.wait_group 0;"); }

// ---------------------------------------------------------------------------
// Q/K/V projections (R12 version — best measured): 128x64 tile, 8x4 microtile,
// single-fill; A at stride 196 (LDS.128), W at stride 194 (conflict-free).
// ---------------------------------------------------------------------------
__global__ void __launch_bounds__(256)
proj_kernel(const float* __restrict__ xin, const float* __restrict__ cin,
            const float* __restrict__ Wq, const float* __restrict__ bq,
            const float* __restrict__ Wk, const float* __restrict__ bk,
            const float* __restrict__ Wv, const float* __restrict__ bv) {
    extern __shared__ float smp[];
    float* a_s = smp;                // [128 t][196 kk]
    float* w_s = smp + 128 * ASTR;   // [64 d][194 kk]
    const int which = blockIdx.z % 3;
    const int b = blockIdx.z / 3;
    const float* in   = (which == 0) ? xin : cin;
    const float* W    = (which == 0) ? Wq : (which == 1) ? Wk : Wv;
    const float* bias = (which == 0) ? bq : (which == 1) ? bk : bv;
    float* out        = (which == 0) ? g_q : (which == 1) ? g_k : g_v;
    const int t0 = blockIdx.x * 128, d0 = blockIdx.y * 64;
    const int tx = threadIdx.x, ty = threadIdx.y, tid = ty * 16 + tx;
    const int lane = tid & 31, wrp = tid >> 5;
    const int la = lane & 3, kl = lane >> 2;
    const float* inb = in + b * Cn * Tn;

#pragma unroll
    for (int r = 0; r < 3; r++) {
        float4 va[8];
#pragma unroll
        for (int ph = 0; ph < 8; ph++) {
            int kk = kl + 8 * wrp + 64 * r;
            int t4 = 4 * la + 16 * ph;
            va[ph] = *reinterpret_cast<const float4*>(inb + kk * Tn + t0 + t4);
        }
#pragma unroll
        for (int ph = 0; ph < 8; ph++) {
            int kk = kl + 8 * wrp + 64 * r;
            int t4 = 4 * la + 16 * ph;
            a_s[(t4 + 0) * ASTR + kk] = va[ph].x;
            a_s[(t4 + 1) * ASTR + kk] = va[ph].y;
            a_s[(t4 + 2) * ASTR + kk] = va[ph].z;
            a_s[(t4 + 3) * ASTR + kk] = va[ph].w;
        }
    }
#pragma unroll
    for (int r = 0; r < 3; r++) {
        float4 vw[4];
#pragma unroll
        for (int ph = 0; ph < 4; ph++) {
            int kk = kl + 8 * wrp + 64 * r;
            int d4 = 4 * la + 16 * ph;
            vw[ph] = *reinterpret_cast<const float4*>(W + kk * Cn + d0 + d4);
        }
#pragma unroll
        for (int ph = 0; ph < 4; ph++) {
            int kk = kl + 8 * wrp + 64 * r;
            int d4 = 4 * la + 16 * ph;
            w_s[(d4 + 0) * WSTR2 + kk] = vw[ph].x;
            w_s[(d4 + 1) * WSTR2 + kk] = vw[ph].y;
            w_s[(d4 + 2) * WSTR2 + kk] = vw[ph].z;
            w_s[(d4 + 3) * WSTR2 + kk] = vw[ph].w;
        }
    }
    __syncthreads();

    u64t acc2[8][4] = {};
#pragma unroll 2
    for (int kk = 0; kk < Cn; kk += 4) {
        float4 a4[8];
        u64t w2[4][2];
#pragma unroll
        for (int i = 0; i < 8; i++)
            a4[i] = *reinterpret_cast<const float4*>(&a_s[(ty + 16 * i) * ASTR + kk]);
#pragma unroll
        for (int j = 0; j < 4; j++) {
            w2[j][0] = lds2(&w_s[(tx + 16 * j) * WSTR2 + kk]);
            w2[j][1] = lds2(&w_s[(tx + 16 * j) * WSTR2 + kk + 2]);
        }
#pragma unroll
        for (int i = 0; i < 8; i++) {
            const u64t* qa = reinterpret_cast<const u64t*>(&a4[i]);
#pragma unroll
            for (int j = 0; j < 4; j++) {
                acc2[i][j] = fma2(qa[0], w2[j][0], acc2[i][j]);
                acc2[i][j] = fma2(qa[1], w2[j][1], acc2[i][j]);
            }
        }
    }
    float* ob = out + b * Tn * Cn;
#pragma unroll
    for (int i = 0; i < 8; i++) {
        int t = t0 + ty + 16 * i;
#pragma unroll
        for (int j = 0; j < 4; j++) {
            int d = d0 + tx + 16 * j;
            ob[t * Cn + d] = lohi_sum(acc2[i][j]) + bias[d];
        }
    }
}

// ---------------------------------------------------------------------------
// Single-pass banded attention (R10 base + prologue-hoisted ballots + paired
// P loads in PV). TQ=64, 2 CTAs/SM, split K/V prefetch.
// ---------------------------------------------------------------------------
__global__ void __launch_bounds__(256, 2)
attn_kernel(const float* __restrict__ embk, const float* __restrict__ embv,
            const int* __restrict__ mask) {
    extern __shared__ float sm[];
    float* qs   = sm;                     // [64][100]
    float* Ks   = qs + TQ * KVS;          // [64][100]
    float* Vs   = Ks + TQ * KVS;          // [64][100]
    float* P    = Vs + TQ * KVS;          // [64][80]
    float* rq   = P + TQ * PSTR;          // [64][12]
    float* pTap = rq + TQ * 12;           // [64][12]
    float* lr   = pTap + TQ * 12;         // [64]
    float* prox = lr + TQ;                // [260]
    u64t*  mrows = reinterpret_cast<u64t*>(prox + 260);  // [9][64]

    const int tx = threadIdx.x, ty = threadIdx.y;
    const int tid = ty * 16 + tx;
    const int lane = tid & 31, wrp = tid >> 5;
    const int b = blockIdx.y / Hn, h = blockIdx.y % Hn;
    const int t0 = blockIdx.x * TQ;
    const int sbase = t0 - BAND;

    const float* Qb = g_q + (b * Tn) * Cn + h * Kd;
    const float* Kb = g_k + (b * Tn) * Cn + h * Kd;
    const float* Vb = g_v + (b * Tn) * Cn + h * Kd;
    const int* mb = mask + b * Tn * Tn;

    // issue chunk 0 K+V loads
#pragma unroll
    for (int r = 0; r < 6; r++) {
        int idx = tid + 256 * r;
        int row = idx / 24, c4 = (idx % 24) * 4;
        int s = sbase + row;
        int sc = s < 0 ? 0 : (s >= Tn ? Tn - 1 : s);
        cpa16(&Ks[row * KVS + c4], Kb + sc * Cn + c4);
        cpa16(&Vs[row * KVS + c4], Vb + sc * Cn + c4);
    }
    cpa_commit();

    for (int i = tid; i < TQ * 12; i += 256) pTap[i] = 0.f;
    for (int i = tid; i <= BAND; i += 256) prox[i] = log1pf((float)i);

    // load Q (pre-scaled)
    const float qsc = 0.10206207261596575f;
#pragma unroll
    for (int r = 0; r < 6; r++) {
        int idx = tid + 256 * r;
        int row = idx / 24, c4 = (idx % 24) * 4;
        float4 v = *reinterpret_cast<const float4*>(Qb + (t0 + row) * Cn + c4);
        float* d = qs + row * KVS + c4;
        d[0] = v.x * qsc; d[1] = v.y * qsc; d[2] = v.z * qsc; d[3] = v.w * qsc;
    }

    // hoist ALL chunk ballots: warp w owns rows 8w..8w+7; coalesced, high MLP
#pragma unroll
    for (int ch = 0; ch < NCH; ch++) {
        int s0 = sbase + ch * 64;
#pragma unroll
        for (int rr = 0; rr < 8; rr++) {
            int t = t0 + 8 * wrp + rr;
            int s1 = s0 + lane, s2 = s0 + lane + 32;
            int d1 = s1 - t, d2 = s2 - t;
            bool v1 = (s1 >= 0) && (s1 < Tn) && (d1 <= BAND) && (d1 >= -BAND);
            bool v2 = (s2 >= 0) && (s2 < Tn) && (d2 <= BAND) && (d2 >= -BAND);
            if (v1) v1 = (mb[t * Tn + s1] != 0);
            if (v2) v2 = (mb[t * Tn + s2] != 0);
            unsigned b1 = __ballot_sync(0xffffffffu, v1);
            unsigned b2 = __ballot_sync(0xffffffffu, v2);
            if (lane == 0) mrows[ch * 64 + 8 * wrp + rr] = ((u64t)b2 << 32) | (u64t)b1;
        }
    }
    __syncthreads();   // qs + mrows visible

    // rel-K per-query logits
    for (int idx = tid; idx < TQ * 9; idx += 256) {
        int q = idx / 9, m = idx - q * 9;
        const float* e  = embk + m * Kd;
        const float* qp = qs + q * KVS;
        float s = 0.f;
#pragma unroll 8
        for (int kk = 0; kk < Kd; kk++) s += qp[kk] * e[kk];
        rq[q * 12 + m] = s;
    }

    float o[4][6] = {};
    float lsum[4] = {};

    for (int ch = 0; ch < NCH; ch++) {
        cpa_wait0();
        __syncthreads();   // Ks/Vs(ch) ready; rq ready (first iter)

        // QK^T, kk paired into f32x2
        u64t acc2[4][4] = {};
#pragma unroll 4
        for (int kk = 0; kk < Kd; kk += 2) {
            u64t q2[4], k2[4];
#pragma unroll
            for (int i = 0; i < 4; i++) q2[i] = lds2(&qs[(ty + 16 * i) * KVS + kk]);
#pragma unroll
            for (int j = 0; j < 4; j++) k2[j] = lds2(&Ks[(tx + 16 * j) * KVS + kk]);
#pragma unroll
            for (int i = 0; i < 4; i++)
#pragma unroll
                for (int j = 0; j < 4; j++) acc2[i][j] = fma2(q2[i], k2[j], acc2[i][j]);
        }

        // epilogue: rel-k tap + proximal bias + mask bit + exp
#pragma unroll
        for (int i = 0; i < 4; i++) {
            int q = ty + 16 * i, t = t0 + q;
            u64t rm = mrows[ch * 64 + q];
#pragma unroll
            for (int j = 0; j < 4; j++) {
                int sl = tx + 16 * j;
                int s = sbase + ch * 64 + sl;
                int d = s - t;
                int ad = d < 0 ? -d : d;
                float v = lohi_sum(acc2[i][j]);
                if (ad <= WIN) v += rq[q * 12 + d + WIN];
                v -= prox[ad <= BAND ? ad : BAND];
                float e = ((rm >> sl) & 1ull) ? __expf(v) : 0.f;
                P[q * PSTR + sl] = e;
                if (ad <= WIN) pTap[q * 12 + d + WIN] = e;
                lsum[i] += e;
            }
        }
        __syncthreads();   // P visible; all warps done with Ks

        // prefetch next K now -> overlaps the PV phase below
        if (ch + 1 < NCH) {
#pragma unroll
            for (int r = 0; r < 6; r++) {
                int idx = tid + 256 * r;
                int row = idx / 24, c4 = (idx % 24) * 4;
                int s = sbase + (ch + 1) * 64 + row;
                int sc = s < 0 ? 0 : (s >= Tn ? Tn - 1 : s);
                cpa16(&Ks[row * KVS + c4], Kb + sc * Cn + c4);
            }
            cpa_commit();
        }

        // O += P @ V: paired P loads (LDS.64 over 2 sl), d-paired V
        {
            u64t o2[4][3] = {};
#pragma unroll 2
            for (int sl = 0; sl < 64; sl += 2) {
                u64t pp[4], va[3], vb[3];
#pragma unroll
                for (int i = 0; i < 4; i++) pp[i] = lds2(&P[(ty + 16 * i) * PSTR + sl]);
#pragma unroll
                for (int jj = 0; jj < 3; jj++) {
                    va[jj] = lds2(&Vs[sl * KVS + 2 * tx + 32 * jj]);
                    vb[jj] = lds2(&Vs[(sl + 1) * KVS + 2 * tx + 32 * jj]);
                }
#pragma unroll
                for (int i = 0; i < 4; i++) {
                    float2 f = unpk(pp[i]);
                    u64t pa = dup2(f.x), pb = dup2(f.y);
#pragma unroll
                    for (int jj = 0; jj < 3; jj++) {
                        o2[i][jj] = fma2(pa, va[jj], o2[i][jj]);
                        o2[i][jj] = fma2(pb, vb[jj], o2[i][jj]);
                    }
                }
            }
#pragma unroll
            for (int i = 0; i < 4; i++)
#pragma unroll
                for (int jj = 0; jj < 3; jj++) {
                    float2 f = unpk(o2[i][jj]);
                    o[i][2 * jj] += f.x;
                    o[i][2 * jj + 1] += f.y;
                }
        }
        __syncthreads();   // PV done with Vs/P

        // now Vs is free: issue next V
        if (ch + 1 < NCH) {
#pragma unroll
            for (int r = 0; r < 6; r++) {
                int idx = tid + 256 * r;
                int row = idx / 24, c4 = (idx % 24) * 4;
                int s = sbase + (ch + 1) * 64 + row;
                int sc = s < 0 ? 0 : (s >= Tn ? Tn - 1 : s);
                cpa16(&Vs[row * KVS + c4], Vb + sc * Cn + c4);
            }
            cpa_commit();
        }
    }

    // reduce row sums across the 16 tx lanes
#pragma unroll
    for (int i = 0; i < 4; i++) {
        float l = lsum[i];
        l += __shfl_xor_sync(0xffffffffu, l, 1);
        l += __shfl_xor_sync(0xffffffffu, l, 2);
        l += __shfl_xor_sync(0xffffffffu, l, 4);
        l += __shfl_xor_sync(0xffffffffu, l, 8);
        if (tx == 0) lr[ty + 16 * i] = l;
    }
    __syncthreads();

    // rel-V taps + normalize + store
#pragma unroll
    for (int i = 0; i < 4; i++) {
        int q = ty + 16 * i;
        float inv = 1.0f / lr[q];
#pragma unroll
        for (int m = 0; m < 9; m++) {
            float p = pTap[q * 12 + m];
#pragma unroll
            for (int jj = 0; jj < 3; jj++) {
                float2 e2 = *reinterpret_cast<const float2*>(embv + m * Kd + 2 * tx + 32 * jj);
                o[i][2 * jj]     += p * e2.x;
                o[i][2 * jj + 1] += p * e2.y;
            }
        }
        float* ob = g_att + (b * Tn + t0 + q) * Cn + h * Kd;
#pragma unroll
        for (int jj = 0; jj < 3; jj++) {
            float2 w;
            w.x = o[i][2 * jj] * inv;
            w.y = o[i][2 * jj + 1] * inv;
            *reinterpret_cast<float2*>(ob + 2 * tx + 32 * jj) = w;
        }
    }
}

// ---------------------------------------------------------------------------
// Output projection + transpose (R7 version, conflict-free strides).
// ---------------------------------------------------------------------------
__global__ void __launch_bounds__(256)
outproj_kernel(const float* __restrict__ Wo, const float* __restrict__ bo,
               float* __restrict__ out) {
    extern __shared__ float smp[];
    float* a_s = smp;                // [64 t][OASTR dd]
    float* w_s = smp + 64 * OASTR;   // [64 co][OWSTR dd]
    const int b = blockIdx.z;
    const int t0 = blockIdx.x * 64, c0 = blockIdx.y * 64;
    const int tx = threadIdx.x, ty = threadIdx.y, tid = ty * 16 + tx;
    const int lane = tid & 31, wrp = tid >> 5;
    const int la = lane & 3, kl = lane >> 2;
    const float* ab = g_att + b * Tn * Cn;

#pragma unroll
    for (int r = 0; r < 12; r++) {
        int idx = tid + 256 * r;
        int t = idx / 48, dq = (idx % 48) * 4;
        cpa16(&a_s[t * OASTR + dq], ab + (t0 + t) * Cn + dq);
    }
    cpa_commit();
    {
        float4 vw[12];
#pragma unroll
        for (int r = 0; r < 3; r++)
#pragma unroll
            for (int ph = 0; ph < 4; ph++) {
                int kk = kl + 8 * wrp + 64 * r;
                int d4 = 4 * la + 16 * ph;
                vw[r * 4 + ph] = *reinterpret_cast<const float4*>(Wo + kk * Cn + c0 + d4);
            }
#pragma unroll
        for (int r = 0; r < 3; r++)
#pragma unroll
            for (int ph = 0; ph < 4; ph++) {
                int kk = kl + 8 * wrp + 64 * r;
                int d4 = 4 * la + 16 * ph;
                float4 v = vw[r * 4 + ph];
                w_s[(d4 + 0) * OWSTR + kk] = v.x;
                w_s[(d4 + 1) * OWSTR + kk] = v.y;
                w_s[(d4 + 2) * OWSTR + kk] = v.z;
                w_s[(d4 + 3) * OWSTR + kk] = v.w;
            }
    }
    cpa_wait0();
    __syncthreads();

    u64t acc2[4][4] = {};
#pragma unroll 8
    for (int kk = 0; kk < Cn; kk += 2) {
        u64t w2[4], a2[4];
#pragma unroll
        for (int i = 0; i < 4; i++) w2[i] = lds2(&w_s[(ty + 16 * i) * OWSTR + kk]);
#pragma unroll
        for (int j = 0; j < 4; j++) a2[j] = lds2(&a_s[(tx + 16 * j) * OASTR + kk]);
#pragma unroll
        for (int i = 0; i < 4; i++)
#pragma unroll
            for (int j = 0; j < 4; j++) acc2[i][j] = fma2(w2[i], a2[j], acc2[i][j]);
    }
#pragma unroll
    for (int i = 0; i < 4; i++) {
        int co = c0 + ty + 16 * i;
        float bb = bo[co];
#pragma unroll
        for (int j = 0; j < 4; j++)
            out[(b * Cn + co) * Tn + t0 + tx + 16 * j] = lohi_sum(acc2[i][j]) + bb;
    }
}

// ---------------------------------------------------------------------------
extern "C" void kernel_launch(void* const* d_in, const int* in_sizes, int n_in,
                              void* d_out, int out_size) {
    (void)in_sizes; (void)n_in; (void)out_size;
    const float* x   = (const float*)d_in[0];
    const float* c   = (const float*)d_in[1];
    const float* Wq  = (const float*)d_in[2];
    const float* bq  = (const float*)d_in[3];
    const float* Wk  = (const float*)d_in[4];
    const float* bk  = (const float*)d_in[5];
    const float* Wv  = (const float*)d_in[6];
    const float* bv  = (const float*)d_in[7];
    const float* Wo  = (const float*)d_in[8];
    const float* bo  = (const float*)d_in[9];
    const float* ek  = (const float*)d_in[10];
    const float* ev  = (const float*)d_in[11];
    const int*   msk = (const int*)d_in[12];

    const int attn_smem = ATTN_SMEM_FLOATS * (int)sizeof(float);
    cudaFuncSetAttribute(attn_kernel, cudaFuncAttributeMaxDynamicSharedMemorySize, attn_smem);
    cudaFuncSetAttribute(proj_kernel, cudaFuncAttributeMaxDynamicSharedMemorySize, GEMM_SMEM_BYTES);
    cudaFuncSetAttribute(outproj_kernel, cudaFuncAttributeMaxDynamicSharedMemorySize, OUT_SMEM_BYTES);

    proj_kernel<<<dim3(Tn / 128, Cn / 64, Bn * 3), dim3(16, 16), GEMM_SMEM_BYTES>>>(
        x, c, Wq, bq, Wk, bk, Wv, bv);
    attn_kernel<<<dim3(Tn / TQ, Bn * Hn), dim3(16, 16), attn_smem>>>(ek, ev, msk);
    outproj_kernel<<<dim3(Tn / 64, Cn / 64, Bn), dim3(16, 16), OUT_SMEM_BYTES>>>(
        Wo, bo, (float*)d_out);
}